// round 6
// baseline (speedup 1.0000x reference)
#include <cuda_runtime.h>
#include <cuda_bf16.h>
#include <cstdint>

#define NN 50000
#define NG 64
#define MAXE 800000
#define MAXH 512
#define BN_EPS 1e-5f
#define SCAN_B 1024

// ================= scratch (device globals) ===================================
__device__ __align__(16) float g_h[(size_t)NN * MAXH];
__device__ __align__(16) float g_agg[(size_t)NN * MAXH];
__device__ __align__(16) __nv_bfloat16 g_ahi[(size_t)NN * MAXH];
__device__ __align__(16) __nv_bfloat16 g_alo[(size_t)NN * MAXH];
__device__ __align__(16) __nv_bfloat16 g_wthi[MAXH * MAXH];
__device__ __align__(16) __nv_bfloat16 g_wtlo[MAXH * MAXH];
__device__ float g_dinv[NN];
__device__ int   g_cnt[NN];
__device__ int   g_cursor[NN];
__device__ int   g_off[NN + 1];
__device__ int   g_bsum[64];
__device__ int   g_csrc[MAXE];
__device__ float g_cw[MAXE];
__device__ double g_sumd[MAXH];
__device__ double g_sqsd[MAXH];
__device__ __align__(16) float g_mean[MAXH];
__device__ __align__(16) float g_scale[MAXH];
__device__ int   g_gstart[NG + 1];

// ================= CSR build ===================================================
__global__ void k_zeroi(int* p, int n) {
    int i = blockIdx.x * blockDim.x + threadIdx.x;
    if (i < n) p[i] = 0;
}
__global__ void k_count(const int* __restrict__ col, int* cnt, int E) {
    int i = blockIdx.x * blockDim.x + threadIdx.x;
    if (i < E) atomicAdd(&cnt[col[i]], 1);
}
__global__ void k_scan1(const int* __restrict__ cnt, int* off, int* bsum, int n) {
    __shared__ int sh[SCAN_B];
    int i = blockIdx.x * SCAN_B + threadIdx.x;
    sh[threadIdx.x] = (i < n) ? cnt[i] : 0;
    __syncthreads();
#pragma unroll
    for (int d = 1; d < SCAN_B; d <<= 1) {
        int t = (threadIdx.x >= d) ? sh[threadIdx.x - d] : 0;
        __syncthreads();
        sh[threadIdx.x] += t;
        __syncthreads();
    }
    if (i < n) off[i + 1] = sh[threadIdx.x];
    if (threadIdx.x == SCAN_B - 1) bsum[blockIdx.x] = sh[SCAN_B - 1];
}
__global__ void k_scan2(int* bsum, int nb, int* off) {
    if (threadIdx.x == 0) {
        off[0] = 0;
        int s = 0;
        for (int b = 0; b < nb; b++) { s += bsum[b]; bsum[b] = s; }
    }
}
__global__ void k_scan3(int* off, const int* __restrict__ bsum, int n) {
    int b = blockIdx.x + 1;
    int i = b * SCAN_B + threadIdx.x;
    if (i < n) off[i + 1] += bsum[b - 1];
}
__global__ void k_dinv2(const int* __restrict__ cnt, float* dinv, int n) {
    int i = blockIdx.x * blockDim.x + threadIdx.x;
    if (i < n) dinv[i] = rsqrtf((float)(cnt[i] + 1));
}
__global__ void k_place(const int* __restrict__ row, const int* __restrict__ col,
                        const float* __restrict__ dinv, const int* __restrict__ off,
                        int* cursor, int* csrc, float* cw, int E) {
    int e = blockIdx.x * blockDim.x + threadIdx.x;
    if (e >= E) return;
    int d = col[e], r = row[e];
    int pos = off[d] + atomicAdd(&cursor[d], 1);
    csrc[pos] = r;
    cw[pos] = dinv[r] * dinv[d];
}

// ================= bf16 split kernels ==========================================
__global__ void k_split_plain(const float* __restrict__ src, __nv_bfloat16* hi,
                              __nv_bfloat16* lo, int total) {
    int i = blockIdx.x * blockDim.x + threadIdx.x;
    if (i >= total) return;
    float v = src[i];
    __nv_bfloat16 h = __float2bfloat16(v);
    hi[i] = h;
    lo[i] = __float2bfloat16(v - __bfloat162float(h));
}
__global__ void k_split_bn(const float* __restrict__ src, __nv_bfloat16* hi,
                           __nv_bfloat16* lo, const float* __restrict__ mean,
                           const float* __restrict__ scale, const float* __restrict__ be,
                           int total, int kmask) {
    int i = blockIdx.x * blockDim.x + threadIdx.x;
    if (i >= total) return;
    int c = i & kmask;
    float v = fmaxf((src[i] - mean[c]) * scale[c] + be[c], 0.f);
    __nv_bfloat16 h = __float2bfloat16(v);
    hi[i] = h;
    lo[i] = __float2bfloat16(v - __bfloat162float(h));
}
// transpose + split: Wt[n*K+k] = W[k*N+n]
__global__ void k_split_wt(const float* __restrict__ W, __nv_bfloat16* hi,
                           __nv_bfloat16* lo, int K, int N) {
    int i = blockIdx.x * blockDim.x + threadIdx.x;
    if (i >= K * N) return;
    int n = i / K, k = i - n * K;
    float v = W[(size_t)k * N + n];
    __nv_bfloat16 h = __float2bfloat16(v);
    hi[i] = h;
    lo[i] = __float2bfloat16(v - __bfloat162float(h));
}

// ================= mma.sync bf16 split GEMM ====================================
// C[M,N] = A@W (A row-major [M,K], Wt row-major [N,K]); K_eff = 3K phases:
//   phase0: Ahi*Bhi, phase1: Alo*Bhi, phase2: Ahi*Blo
// CTA tile 128x128; 8 warps, warp tile 64x32. KC=64 per chunk.
// Epilogue: H = C ; AGG = C*dinv[row]^2 + bias[col]
#define KC 64
#define TSTR 72                         // bf16 elems per tile row (144B, conflict-free)
#define TILE_E (128 * TSTR)             // elems per tile
#define SMEM_GEMM (2 * 2 * TILE_E * 2)  // 2 bufs x (A+B) x bf16 = 73728 B

__device__ __forceinline__ uint32_t smem_u32(const void* p) {
    uint32_t a;
    asm("{ .reg .u64 t; cvta.to.shared.u64 t, %1; cvt.u32.u64 %0, t; }"
        : "=r"(a) : "l"(p));
    return a;
}

__device__ __forceinline__ void ldsm_x4(uint32_t* r, uint32_t addr) {
    asm volatile("ldmatrix.sync.aligned.m8n8.x4.shared.b16 {%0,%1,%2,%3}, [%4];"
                 : "=r"(r[0]), "=r"(r[1]), "=r"(r[2]), "=r"(r[3]) : "r"(addr));
}
__device__ __forceinline__ void ldsm_x2(uint32_t* r, uint32_t addr) {
    asm volatile("ldmatrix.sync.aligned.m8n8.x2.shared.b16 {%0,%1}, [%2];"
                 : "=r"(r[0]), "=r"(r[1]) : "r"(addr));
}
__device__ __forceinline__ void mma16816(float* c, const uint32_t* a, const uint32_t* b) {
    asm volatile(
        "mma.sync.aligned.m16n8k16.row.col.f32.bf16.bf16.f32 "
        "{%0,%1,%2,%3}, {%4,%5,%6,%7}, {%8,%9}, {%0,%1,%2,%3};"
        : "+f"(c[0]), "+f"(c[1]), "+f"(c[2]), "+f"(c[3])
        : "r"(a[0]), "r"(a[1]), "r"(a[2]), "r"(a[3]), "r"(b[0]), "r"(b[1]));
}

// load one 128xKC bf16 tile (rows rowBase.., guarded by Mlim) into smem tile tb
__device__ __forceinline__ void load_tile(char* sm, int tb,
                                          const __nv_bfloat16* __restrict__ src,
                                          int rowBase, int Mlim, int K, int k0, int tid) {
#pragma unroll
    for (int it = 0; it < 8; it++) {
        int q = it * 256 + tid;
        int r = q >> 4;                  // 0..127
        int kc = (q & 15) << 2;          // bf16 col, step 4
        uint2 v = make_uint2(0u, 0u);
        int grow = rowBase + r;
        if (grow < Mlim)
            v = *(const uint2*)(src + (size_t)grow * K + k0 + kc);
        *(uint2*)(sm + tb + (r * TSTR + kc) * 2) = v;
    }
}

__global__ __launch_bounds__(256, 2)
void k_mma_gemm(const __nv_bfloat16* __restrict__ Ahi, const __nv_bfloat16* __restrict__ Alo,
                const __nv_bfloat16* __restrict__ Bhi, const __nv_bfloat16* __restrict__ Blo,
                float* __restrict__ Hout, float* __restrict__ AGG,
                const float* __restrict__ dinv, const float* __restrict__ bias,
                int M, int K, int N) {
    extern __shared__ char sm[];
    const uint32_t sb = smem_u32(sm);
    const int tid = threadIdx.x;
    const int wid = tid >> 5;
    const int lane = tid & 31;
    const int rowBase = blockIdx.y * 128;
    const int colBase = blockIdx.x * 128;

    const int warp_m = wid & 1;          // 2 x 64 rows
    const int warp_n = wid >> 1;         // 4 x 32 cols

    // tile offsets (bytes): buf b: A at b*(2*TILE_E*2), B after A
    const int bufA[2] = {0, 4 * TILE_E};
    const int bufB[2] = {2 * TILE_E, 6 * TILE_E};

    const int nk = K / KC;
    const int NC = 3 * nk;

    float acc[4][4][4] = {};             // [mf][nf][reg]

    // chunk source selector
    auto srcA = [&](int phase) { return (phase == 1) ? Alo : Ahi; };
    auto srcB = [&](int phase) { return (phase == 2) ? Blo : Bhi; };

    // preload chunk 0
    load_tile(sm, bufA[0], Ahi, rowBase, M, K, 0, tid);
    load_tile(sm, bufB[0], Bhi, colBase, N, K, 0, tid);
    __syncthreads();

    // ldmatrix lane addressing (within-warp constants)
    const int a_row = warp_m * 64 + (lane & 7) + ((lane >> 3) & 1) * 8;  // + mf*16
    const int a_col = ((lane >> 4) & 1) * 8;                              // + ks*16
    const int b_row = warp_n * 32 + (lane & 7);                           // + nf*8
    const int b_col = ((lane >> 3) & 1) * 8;                              // + ks*16

    for (int c = 0; c < NC; c++) {
        int b = c & 1;
        if (c + 1 < NC) {
            int cn = c + 1;
            int phase = cn / nk;
            int k0 = (cn - phase * nk) * KC;
            load_tile(sm, bufA[b ^ 1], srcA(phase), rowBase, M, K, k0, tid);
            load_tile(sm, bufB[b ^ 1], srcB(phase), colBase, N, K, k0, tid);
        }

        uint32_t Abase = sb + bufA[b];
        uint32_t Bbase = sb + bufB[b];
#pragma unroll
        for (int ks = 0; ks < 4; ks++) {
            uint32_t afr[4][4], bfr[4][2];
#pragma unroll
            for (int mf = 0; mf < 4; mf++)
                ldsm_x4(afr[mf],
                        Abase + (((a_row + mf * 16) * TSTR) + a_col + ks * 16) * 2);
#pragma unroll
            for (int nf = 0; nf < 4; nf++)
                ldsm_x2(bfr[nf],
                        Bbase + (((b_row + nf * 8) * TSTR) + b_col + ks * 16) * 2);
#pragma unroll
            for (int mf = 0; mf < 4; mf++)
#pragma unroll
                for (int nf = 0; nf < 4; nf++)
                    mma16816(acc[mf][nf], afr[mf], bfr[nf]);
        }
        __syncthreads();
    }

    // epilogue: fragment layout: rows gid, gid+8; cols tg*2, tg*2+1
    const int gid = lane >> 2;
    const int tg = lane & 3;
#pragma unroll
    for (int mf = 0; mf < 4; mf++) {
#pragma unroll
        for (int half = 0; half < 2; half++) {
            int gr = rowBase + warp_m * 64 + mf * 16 + gid + half * 8;
            if (gr >= M) continue;
            float di = dinv[gr];
            float d2 = di * di;
            size_t base = (size_t)gr * N;
#pragma unroll
            for (int nf = 0; nf < 4; nf++) {
                int gc = colBase + warp_n * 32 + nf * 8 + tg * 2;
                float c0 = acc[mf][nf][half * 2 + 0];
                float c1 = acc[mf][nf][half * 2 + 1];
                *(float2*)&Hout[base + gc] = make_float2(c0, c1);
                float b0 = bias[gc], b1 = bias[gc + 1];
                *(float2*)&AGG[base + gc] =
                    make_float2(c0 * d2 + b0, c1 * d2 + b1);
            }
        }
    }
}

// ================= CSR gather ===================================================
__global__ void k_gather(const float* __restrict__ h, const int* __restrict__ csrc,
                         const float* __restrict__ cw, const int* __restrict__ off,
                         float* __restrict__ agg, int H, int tpnshift) {
    int tpn = 1 << tpnshift;
    int local = threadIdx.x >> tpnshift;
    int node = blockIdx.x * (blockDim.x >> tpnshift) + local;
    if (node >= NN) return;
    int c = (threadIdx.x & (tpn - 1)) << 2;
    int s = __ldg(&off[node]);
    int e = __ldg(&off[node + 1]);
    float ax = 0.f, ay = 0.f, az = 0.f, aw = 0.f;
    for (int i = s; i < e; i++) {
        int src = __ldg(&csrc[i]);
        float w = __ldg(&cw[i]);
        float4 v = __ldg((const float4*)(h + (size_t)src * H + c));
        ax += v.x * w; ay += v.y * w; az += v.z * w; aw += v.w * w;
    }
    float4 cur = *(float4*)&agg[(size_t)node * H + c];
    cur.x += ax; cur.y += ay; cur.z += az; cur.w += aw;
    *(float4*)&agg[(size_t)node * H + c] = cur;
}

// ================= BN statistics (fp64 accumulate) ==============================
__global__ void k_zerod(double* a, double* b, int n) {
    int i = blockIdx.x * blockDim.x + threadIdx.x;
    if (i < n) { a[i] = 0.0; b[i] = 0.0; }
}
__global__ void k_stats(const float* __restrict__ x, int rows, int H,
                        double* __restrict__ sum, double* __restrict__ sqs) {
    int c = blockIdx.x * blockDim.x + threadIdx.x;
    if (c >= H) return;
    double s = 0.0, q = 0.0;
    for (int r = blockIdx.y; r < rows; r += gridDim.y) {
        double v = (double)x[(size_t)r * H + c];
        s += v;
        q += v * v;
    }
    atomicAdd(&sum[c], s);
    atomicAdd(&sqs[c], q);
}
__global__ void k_bnparam(const double* __restrict__ sum, const double* __restrict__ sqs,
                          const float* __restrict__ g, float* __restrict__ mean,
                          float* __restrict__ scale, int H) {
    int c = blockIdx.x * blockDim.x + threadIdx.x;
    if (c >= H) return;
    const double invN = 1.0 / (double)NN;
    double m = sum[c] * invN;
    double var = sqs[c] * invN - m * m;
    mean[c] = (float)m;
    scale[c] = g[c] * (float)rsqrt(var + (double)BN_EPS);
}

// ================= graph boundaries + pool head =================================
__global__ void k_bounds(const int* __restrict__ batch, int* gstart, int n) {
    int i = blockIdx.x * blockDim.x + threadIdx.x;
    if (i >= n) return;
    int bi = batch[i];
    int bp = (i == 0) ? -1 : batch[i - 1];
    for (int g = bp + 1; g <= bi; g++) gstart[g] = i;
    if (i == n - 1)
        for (int g = bi + 1; g <= NG; g++) gstart[g] = n;
}
__global__ void k_pool_head(const float* __restrict__ agg, const int* __restrict__ gstart,
                            const float* __restrict__ mean, const float* __restrict__ scale,
                            const float* __restrict__ be, const float* __restrict__ Wo,
                            const float* __restrict__ bo, float* __restrict__ out) {
    __shared__ float pooled[128];
    int g = blockIdx.x;
    int c = threadIdx.x;
    int s = gstart[g], e = gstart[g + 1];
    float mn = mean[c], sc = scale[c], bb = be[c];
    float acc = 0.f;
    for (int n = s; n < e; n++)
        acc += fmaxf((agg[(size_t)n * 128 + c] - mn) * sc + bb, 0.f);
    float inv = 1.0f / (float)max(e - s, 1);
    pooled[c] = acc * inv;
    __syncthreads();
    if (c < 10) {
        float o = bo[c];
#pragma unroll 8
        for (int k = 0; k < 128; k++)
            o += pooled[k] * Wo[k * 10 + c];
        out[g * 10 + c] = o;
    }
}

// ================= host orchestration ===========================================
static inline int ilog2(int v) { int s = 0; while ((1 << s) < v) s++; return s; }

struct Ptrs {
    float *h, *agg, *dinv, *mean, *scale, *cw;
    __nv_bfloat16 *ahi, *alo, *wthi, *wtlo;
    double *sumd, *sqsd;
    int *cnt, *cursor, *off, *bsum, *csrc, *gstart;
};

static void run_layer(int K, int N, const float* W, const float* b, const Ptrs& p) {
    int wtot = K * N;
    k_split_wt<<<(wtot + 255) / 256, 256>>>(W, p.wthi, p.wtlo, K, N);

    dim3 grid(N / 128, (NN + 127) / 128);
    k_mma_gemm<<<grid, 256, SMEM_GEMM>>>(p.ahi, p.alo, p.wthi, p.wtlo,
                                         p.h, p.agg, p.dinv, b, NN, K, N);

    int tpnshift = ilog2(N / 4);
    int npb = 128 >> tpnshift;
    k_gather<<<(NN + npb - 1) / npb, 128>>>(p.h, p.csrc, p.cw, p.off, p.agg, N, tpnshift);

    k_zerod<<<(N + 127) / 128, 128>>>(p.sumd, p.sqsd, N);
    dim3 sgrid((N + 255) / 256, 512);
    k_stats<<<sgrid, 256>>>(p.agg, NN, N, p.sumd, p.sqsd);
}

extern "C" void kernel_launch(void* const* d_in, const int* in_sizes, int n_in,
                              void* d_out, int out_size) {
    const float* x     = (const float*)d_in[0];
    const int*   ei    = (const int*)d_in[1];
    const int*   batch = (const int*)d_in[2];
    const float* W1 = (const float*)d_in[3];  const float* b1 = (const float*)d_in[4];
    const float* g1 = (const float*)d_in[5];  const float* be1 = (const float*)d_in[6];
    const float* W2 = (const float*)d_in[7];  const float* b2 = (const float*)d_in[8];
    const float* g2 = (const float*)d_in[9];  const float* be2 = (const float*)d_in[10];
    const float* W3 = (const float*)d_in[11]; const float* b3 = (const float*)d_in[12];
    const float* g3 = (const float*)d_in[13]; const float* be3 = (const float*)d_in[14];
    const float* Wo = (const float*)d_in[15]; const float* bo = (const float*)d_in[16];
    float* out = (float*)d_out;

    int E = in_sizes[1] / 2;
    const int* row = ei;
    const int* col = ei + E;

    Ptrs p;
    cudaGetSymbolAddress((void**)&p.h, g_h);
    cudaGetSymbolAddress((void**)&p.agg, g_agg);
    cudaGetSymbolAddress((void**)&p.ahi, g_ahi);
    cudaGetSymbolAddress((void**)&p.alo, g_alo);
    cudaGetSymbolAddress((void**)&p.wthi, g_wthi);
    cudaGetSymbolAddress((void**)&p.wtlo, g_wtlo);
    cudaGetSymbolAddress((void**)&p.dinv, g_dinv);
    cudaGetSymbolAddress((void**)&p.sumd, g_sumd);
    cudaGetSymbolAddress((void**)&p.sqsd, g_sqsd);
    cudaGetSymbolAddress((void**)&p.mean, g_mean);
    cudaGetSymbolAddress((void**)&p.scale, g_scale);
    cudaGetSymbolAddress((void**)&p.cw, g_cw);
    cudaGetSymbolAddress((void**)&p.cnt, g_cnt);
    cudaGetSymbolAddress((void**)&p.cursor, g_cursor);
    cudaGetSymbolAddress((void**)&p.off, g_off);
    cudaGetSymbolAddress((void**)&p.bsum, g_bsum);
    cudaGetSymbolAddress((void**)&p.csrc, g_csrc);
    cudaGetSymbolAddress((void**)&p.gstart, g_gstart);

    cudaFuncSetAttribute(k_mma_gemm, cudaFuncAttributeMaxDynamicSharedMemorySize,
                         SMEM_GEMM);

    // ---- CSR build + dinv ----
    int nb = (NN + SCAN_B - 1) / SCAN_B;
    k_zeroi<<<(NN + 255) / 256, 256>>>(p.cnt, NN);
    k_count<<<(E + 255) / 256, 256>>>(col, p.cnt, E);
    k_scan1<<<nb, SCAN_B>>>(p.cnt, p.off, p.bsum, NN);
    k_scan2<<<1, 32>>>(p.bsum, nb, p.off);
    if (nb > 1) k_scan3<<<nb - 1, SCAN_B>>>(p.off, p.bsum, NN);
    k_dinv2<<<(NN + 255) / 256, 256>>>(p.cnt, p.dinv, NN);
    k_zeroi<<<(NN + 255) / 256, 256>>>(p.cursor, NN);
    k_place<<<(E + 255) / 256, 256>>>(row, col, p.dinv, p.off, p.cursor, p.csrc, p.cw, E);
    k_bounds<<<(NN + 255) / 256, 256>>>(batch, p.gstart, NN);

    // ---- layer 1 ----
    k_split_plain<<<(NN * 128 + 255) / 256, 256>>>(x, p.ahi, p.alo, NN * 128);
    run_layer(128, 512, W1, b1, p);

    // ---- layer 2 ----
    k_bnparam<<<(512 + 127) / 128, 128>>>(p.sumd, p.sqsd, g1, p.mean, p.scale, 512);
    k_split_bn<<<(NN * 512 + 255) / 256, 256>>>(p.agg, p.ahi, p.alo, p.mean, p.scale,
                                                be1, NN * 512, 511);
    run_layer(512, 256, W2, b2, p);

    // ---- layer 3 ----
    k_bnparam<<<(256 + 127) / 128, 128>>>(p.sumd, p.sqsd, g2, p.mean, p.scale, 256);
    k_split_bn<<<(NN * 256 + 255) / 256, 256>>>(p.agg, p.ahi, p.alo, p.mean, p.scale,
                                                be2, NN * 256, 255);
    run_layer(256, 128, W3, b3, p);

    // ---- final BN + pool + head ----
    k_bnparam<<<1, 128>>>(p.sumd, p.sqsd, g3, p.mean, p.scale, 128);
    k_pool_head<<<NG, 128>>>(p.agg, p.gstart, p.mean, p.scale, be3, Wo, bo, out);
}